// round 1
// baseline (speedup 1.0000x reference)
#include <cuda_runtime.h>
#include <cstddef>

#define N0  2048
#define NN1 3072
#define DM  1024
#define NH  16
#define DKH 64

// ---------------- scratch (device globals; no allocation) ----------------
__device__ float g_Q [(size_t)N0 * DM];
__device__ float g_K [(size_t)N0 * DM];
__device__ float g_V [(size_t)N0 * DM];
__device__ float g_Q1[(size_t)NN1 * DM];
__device__ float g_K1[(size_t)NN1 * DM];
__device__ float g_V1[(size_t)NN1 * DM];
__device__ float g_S [(size_t)NH * NN1 * N0];   // 403 MB, reused by both directions
__device__ float g_C [(size_t)NN1 * DM];        // dir1 context, [H][DK][N1] flat
__device__ float g_C1[(size_t)N0 * DM];         // dir2 context, [H][DK][N0] flat

// ---------------- NN GEMM: C[M,N] = A[M,K] @ B[K,N], tight row-major ------
// 128x128 block tile, BK=16, 256 threads, 8x8 per thread. All dims divide.
__global__ void __launch_bounds__(256) gemm_nn(
    const float* __restrict__ A, const float* __restrict__ B,
    float* __restrict__ C, int M, int N, int K)
{
    const int BM = 128, BN = 128, BK = 16;
    __shared__ float As[BK][BM];
    __shared__ float Bs[BK][BN];

    const int tid = threadIdx.x;
    const int tx = tid % 16, ty = tid / 16;
    const int bm = blockIdx.y * BM, bn = blockIdx.x * BN;

    float acc[8][8] = {};

    for (int k0 = 0; k0 < K; k0 += BK) {
        // A tile: BM x BK, stored transposed As[k][m]
        #pragma unroll
        for (int p = 0; p < 2; p++) {
            int v = tid + p * 256;          // 512 float4 = 2048 floats
            int m = v / 4;                  // 4 float4 per 16-wide row
            int kk = (v % 4) * 4;
            float4 a = *(const float4*)&A[(size_t)(bm + m) * K + k0 + kk];
            As[kk + 0][m] = a.x; As[kk + 1][m] = a.y;
            As[kk + 2][m] = a.z; As[kk + 3][m] = a.w;
        }
        // B tile: BK x BN, direct
        #pragma unroll
        for (int p = 0; p < 2; p++) {
            int v = tid + p * 256;
            int kk = v / 32;                // 32 float4 per 128-wide row
            int n = (v % 32) * 4;
            *(float4*)&Bs[kk][n] = *(const float4*)&B[(size_t)(k0 + kk) * N + bn + n];
        }
        __syncthreads();

        #pragma unroll
        for (int k = 0; k < BK; k++) {
            float4 a0 = *(const float4*)&As[k][ty * 8];
            float4 a1 = *(const float4*)&As[k][ty * 8 + 4];
            float4 b0 = *(const float4*)&Bs[k][tx * 8];
            float4 b1 = *(const float4*)&Bs[k][tx * 8 + 4];
            float a[8] = {a0.x, a0.y, a0.z, a0.w, a1.x, a1.y, a1.z, a1.w};
            float b[8] = {b0.x, b0.y, b0.z, b0.w, b1.x, b1.y, b1.z, b1.w};
            #pragma unroll
            for (int i = 0; i < 8; i++)
                #pragma unroll
                for (int j = 0; j < 8; j++)
                    acc[i][j] += a[i] * b[j];
        }
        __syncthreads();
    }

    #pragma unroll
    for (int i = 0; i < 8; i++) {
        int m = bm + ty * 8 + i;
        *(float4*)&C[(size_t)m * N + bn + tx * 8]     =
            make_float4(acc[i][0], acc[i][1], acc[i][2], acc[i][3]);
        *(float4*)&C[(size_t)m * N + bn + tx * 8 + 4] =
            make_float4(acc[i][4], acc[i][5], acc[i][6], acc[i][7]);
    }
}

// ------- scores (NT, batched over heads): S[h] = scale * Qh @ Kh^T --------
// A = Qb + h*64 (M x 64, ld DM), B = Kb + h*64 (N x 64, ld DM), C = Sb + h*M*N
__global__ void __launch_bounds__(256) gemm_nt_heads(
    const float* __restrict__ Qb, const float* __restrict__ Kb,
    float* __restrict__ Sb, int M, int N, float scale)
{
    const int BM = 128, BN = 128, BK = 16;
    const int h = blockIdx.z;
    const float* A = Qb + h * DKH;
    const float* B = Kb + h * DKH;
    float* C = Sb + (size_t)h * M * N;

    const int tid = threadIdx.x;
    const int tx = tid % 16, ty = tid / 16;
    const int bm = blockIdx.y * BM, bn = blockIdx.x * BN;

    __shared__ float As[BK][BM];
    __shared__ float Bs[BK][BN];

    float acc[8][8] = {};

    for (int k0 = 0; k0 < DKH; k0 += BK) {
        #pragma unroll
        for (int p = 0; p < 2; p++) {
            int v = tid + p * 256;          // 512 float4
            int r = v / 4;                  // row within 128
            int kk = (v % 4) * 4;
            float4 a = *(const float4*)&A[(size_t)(bm + r) * DM + k0 + kk];
            As[kk + 0][r] = a.x; As[kk + 1][r] = a.y;
            As[kk + 2][r] = a.z; As[kk + 3][r] = a.w;
            float4 b = *(const float4*)&B[(size_t)(bn + r) * DM + k0 + kk];
            Bs[kk + 0][r] = b.x; Bs[kk + 1][r] = b.y;
            Bs[kk + 2][r] = b.z; Bs[kk + 3][r] = b.w;
        }
        __syncthreads();

        #pragma unroll
        for (int k = 0; k < BK; k++) {
            float4 a0 = *(const float4*)&As[k][ty * 8];
            float4 a1 = *(const float4*)&As[k][ty * 8 + 4];
            float4 b0 = *(const float4*)&Bs[k][tx * 8];
            float4 b1 = *(const float4*)&Bs[k][tx * 8 + 4];
            float a[8] = {a0.x, a0.y, a0.z, a0.w, a1.x, a1.y, a1.z, a1.w};
            float b[8] = {b0.x, b0.y, b0.z, b0.w, b1.x, b1.y, b1.z, b1.w};
            #pragma unroll
            for (int i = 0; i < 8; i++)
                #pragma unroll
                for (int j = 0; j < 8; j++)
                    acc[i][j] += a[i] * b[j];
        }
        __syncthreads();
    }

    #pragma unroll
    for (int i = 0; i < 8; i++) {
        int m = bm + ty * 8 + i;
        *(float4*)&C[(size_t)m * N + bn + tx * 8] = make_float4(
            acc[i][0] * scale, acc[i][1] * scale, acc[i][2] * scale, acc[i][3] * scale);
        *(float4*)&C[(size_t)m * N + bn + tx * 8 + 4] = make_float4(
            acc[i][4] * scale, acc[i][5] * scale, acc[i][6] * scale, acc[i][7] * scale);
    }
}

// ------------- row softmax in place; L = NV*1024, one block/row ----------
template <int NV>
__global__ void __launch_bounds__(256) softmax_rows(float* __restrict__ S)
{
    const int L = NV * 1024;
    float* p = S + (size_t)blockIdx.x * L;
    const int tid = threadIdx.x;

    float4 v[NV];
    float mx = -1e30f;
    #pragma unroll
    for (int i = 0; i < NV; i++) {
        v[i] = *(const float4*)&p[(i * 256 + tid) * 4];
        mx = fmaxf(mx, fmaxf(fmaxf(v[i].x, v[i].y), fmaxf(v[i].z, v[i].w)));
    }

    __shared__ float redm[8], reds[8];
    #pragma unroll
    for (int o = 16; o > 0; o >>= 1) mx = fmaxf(mx, __shfl_xor_sync(0xffffffffu, mx, o));
    if ((tid & 31) == 0) redm[tid >> 5] = mx;
    __syncthreads();
    if (tid < 32) {
        float m = (tid < 8) ? redm[tid] : -1e30f;
        #pragma unroll
        for (int o = 4; o > 0; o >>= 1) m = fmaxf(m, __shfl_xor_sync(0xffffffffu, m, o));
        if (tid == 0) redm[0] = m;
    }
    __syncthreads();
    mx = redm[0];

    float sum = 0.f;
    #pragma unroll
    for (int i = 0; i < NV; i++) {
        v[i].x = __expf(v[i].x - mx);
        v[i].y = __expf(v[i].y - mx);
        v[i].z = __expf(v[i].z - mx);
        v[i].w = __expf(v[i].w - mx);
        sum += v[i].x + v[i].y + v[i].z + v[i].w;
    }
    #pragma unroll
    for (int o = 16; o > 0; o >>= 1) sum += __shfl_xor_sync(0xffffffffu, sum, o);
    if ((tid & 31) == 0) reds[tid >> 5] = sum;
    __syncthreads();
    if (tid < 32) {
        float s = (tid < 8) ? reds[tid] : 0.f;
        #pragma unroll
        for (int o = 4; o > 0; o >>= 1) s += __shfl_xor_sync(0xffffffffu, s, o);
        if (tid == 0) reds[0] = s;
    }
    __syncthreads();
    const float inv = 1.0f / reds[0];

    #pragma unroll
    for (int i = 0; i < NV; i++) {
        v[i].x *= inv; v[i].y *= inv; v[i].z *= inv; v[i].w *= inv;
        *(float4*)&p[(i * 256 + tid) * 4] = v[i];
    }
}

// ---- PV (batched heads) with TRANSPOSED store: Ct[(h*64+d)*Nq + q] -------
// P = Pb + h*Nq*Nk (Nq x Nk), V = Vb + h*64 (Nk x 64, ld DM)
__global__ void __launch_bounds__(256) pv_heads(
    const float* __restrict__ Pb, const float* __restrict__ Vb,
    float* __restrict__ Ct, int Nq, int Nk)
{
    const int BM = 128, BK = 32;
    const int h = blockIdx.z;
    const float* P = Pb + (size_t)h * Nq * Nk;
    const float* V = Vb + h * DKH;
    const int bq = blockIdx.y * BM;

    __shared__ float Ps[BK][BM];
    __shared__ float Vs[BK][DKH];

    const int tid = threadIdx.x;
    const int tx = tid % 16, ty = tid / 16;   // tx -> d (16*4=64), ty -> q (16*8=128)

    float acc[8][4] = {};

    for (int k0 = 0; k0 < Nk; k0 += BK) {
        #pragma unroll
        for (int p = 0; p < 4; p++) {          // 1024 float4 for P tile
            int v = tid + p * 256;
            int q = v / 8;                     // 8 float4 per 32-wide row
            int kk = (v % 8) * 4;
            float4 a = *(const float4*)&P[(size_t)(bq + q) * Nk + k0 + kk];
            Ps[kk + 0][q] = a.x; Ps[kk + 1][q] = a.y;
            Ps[kk + 2][q] = a.z; Ps[kk + 3][q] = a.w;
        }
        #pragma unroll
        for (int p = 0; p < 2; p++) {          // 512 float4 for V tile
            int v = tid + p * 256;
            int kk = v / 16;                   // 16 float4 per 64-wide row
            int d = (v % 16) * 4;
            *(float4*)&Vs[kk][d] = *(const float4*)&V[(size_t)(k0 + kk) * DM + d];
        }
        __syncthreads();

        #pragma unroll
        for (int k = 0; k < BK; k++) {
            float4 a0 = *(const float4*)&Ps[k][ty * 8];
            float4 a1 = *(const float4*)&Ps[k][ty * 8 + 4];
            float4 bv = *(const float4*)&Vs[k][tx * 4];
            float a[8] = {a0.x, a0.y, a0.z, a0.w, a1.x, a1.y, a1.z, a1.w};
            float b[4] = {bv.x, bv.y, bv.z, bv.w};
            #pragma unroll
            for (int i = 0; i < 8; i++)
                #pragma unroll
                for (int j = 0; j < 4; j++)
                    acc[i][j] += a[i] * b[j];
        }
        __syncthreads();
    }

    #pragma unroll
    for (int i = 0; i < 8; i++) {
        int q = bq + ty * 8 + i;
        #pragma unroll
        for (int j = 0; j < 4; j++) {
            int d = tx * 4 + j;
            Ct[(size_t)(h * DKH + d) * Nq + q] = acc[i][j];
        }
    }
}

// --------------------------------- launch ---------------------------------
extern "C" void kernel_launch(void* const* d_in, const int* in_sizes, int n_in,
                              void* d_out, int out_size)
{
    const float* X    = (const float*)d_in[0];
    const float* X1   = (const float*)d_in[1];
    const float* WQ   = (const float*)d_in[2];
    const float* WK   = (const float*)d_in[3];
    const float* WV   = (const float*)d_in[4];
    const float* WQ1  = (const float*)d_in[5];
    const float* WK1  = (const float*)d_in[6];
    const float* WV1  = (const float*)d_in[7];
    const float* Wfc  = (const float*)d_in[8];
    const float* Wfc1 = (const float*)d_in[9];
    float* out = (float*)d_out;

    float *Q, *K, *V, *Q1, *K1, *V1, *S, *C, *C1;
    cudaGetSymbolAddress((void**)&Q,  g_Q);
    cudaGetSymbolAddress((void**)&K,  g_K);
    cudaGetSymbolAddress((void**)&V,  g_V);
    cudaGetSymbolAddress((void**)&Q1, g_Q1);
    cudaGetSymbolAddress((void**)&K1, g_K1);
    cudaGetSymbolAddress((void**)&V1, g_V1);
    cudaGetSymbolAddress((void**)&S,  g_S);
    cudaGetSymbolAddress((void**)&C,  g_C);
    cudaGetSymbolAddress((void**)&C1, g_C1);

    const dim3 blk(256);
    const float scale = 0.125f;   // 1/sqrt(64)

    // projections
    gemm_nn<<<dim3(DM / 128, N0 / 128),  blk>>>(X,  WQ,  Q,  N0,  DM, DM);
    gemm_nn<<<dim3(DM / 128, N0 / 128),  blk>>>(X,  WK,  K,  N0,  DM, DM);
    gemm_nn<<<dim3(DM / 128, N0 / 128),  blk>>>(X,  WV,  V,  N0,  DM, DM);
    gemm_nn<<<dim3(DM / 128, NN1 / 128), blk>>>(X1, WQ1, Q1, NN1, DM, DM);
    gemm_nn<<<dim3(DM / 128, NN1 / 128), blk>>>(X1, WK1, K1, NN1, DM, DM);
    gemm_nn<<<dim3(DM / 128, NN1 / 128), blk>>>(X1, WV1, V1, NN1, DM, DM);

    // direction 1: queries from X1 (N1 rows) attend over X (N0 keys)
    gemm_nt_heads<<<dim3(N0 / 128, NN1 / 128, NH), blk>>>(Q1, K, S, NN1, N0, scale);
    softmax_rows<2><<<NH * NN1, 256>>>(S);                       // L = 2048
    pv_heads<<<dim3(1, NN1 / 128, NH), blk>>>(S, V, C, NN1, N0);

    // direction 2: queries from X (N0 rows) attend over X1 (N1 keys)
    gemm_nt_heads<<<dim3(NN1 / 128, N0 / 128, NH), blk>>>(Q, K1, S, N0, NN1, scale);
    softmax_rows<3><<<NH * N0, 256>>>(S);                        // L = 3072
    pv_heads<<<dim3(1, N0 / 128, NH), blk>>>(S, V1, C1, N0, NN1);

    // final FCs (scrambled reshape == flat view of [H][DK][Nq] context)
    gemm_nn<<<dim3(DM / 128, NN1 / 128), blk>>>(C,  Wfc,  out,                  NN1, DM, DM);
    gemm_nn<<<dim3(DM / 128, N0 / 128),  blk>>>(C1, Wfc1, out + (size_t)NN1 * DM, N0,  DM, DM);
}

// round 2
// speedup vs baseline: 2.2410x; 2.2410x over previous
#include <cuda_runtime.h>
#include <cstdint>
#include <cstddef>

#define N0  2048
#define NN1 3072
#define DM  1024
#define NH  16
#define DKH 64

// ---------------- scratch (device globals; no allocation) ----------------
__device__ float g_Q [(size_t)N0 * DM];
__device__ float g_K [(size_t)N0 * DM];
__device__ float g_V [(size_t)N0 * DM];
__device__ float g_Q1[(size_t)NN1 * DM];
__device__ float g_K1[(size_t)NN1 * DM];
__device__ float g_V1[(size_t)NN1 * DM];
__device__ float g_S [(size_t)NH * NN1 * N0];   // 403 MB, reused both directions
__device__ float g_C [(size_t)NN1 * DM];        // dir1 context, [H][DK][N1] flat
__device__ float g_C1[(size_t)N0 * DM];         // dir2 context, [H][DK][N0] flat

// --------------------------- tf32 helpers --------------------------------
__device__ __forceinline__ uint32_t f2t(float f) {
    uint32_t r;
    asm("cvt.rna.tf32.f32 %0, %1;" : "=r"(r) : "f"(f));
    return r;
}

__device__ __forceinline__ void mma8(float c[4], const uint32_t a[4], const uint32_t b[2]) {
    asm volatile(
        "mma.sync.aligned.m16n8k8.row.col.f32.tf32.tf32.f32 "
        "{%0,%1,%2,%3}, {%4,%5,%6,%7}, {%8,%9}, {%0,%1,%2,%3};"
        : "+f"(c[0]), "+f"(c[1]), "+f"(c[2]), "+f"(c[3])
        : "r"(a[0]), "r"(a[1]), "r"(a[2]), "r"(a[3]), "r"(b[0]), "r"(b[1]));
}

// ---------------- NN GEMM (tf32 MMA): C[M,N] = A[M,K] @ B[K,N] ------------
// 128x128 tile, BK=32, 8 warps (2m x 4n), warp tile 64x32.
__global__ void __launch_bounds__(256) gemm_nn_tf32(
    const float* __restrict__ A, const float* __restrict__ B,
    float* __restrict__ C, int M, int N, int K)
{
    const int AP = 36, BP = 136;                 // padded smem row lengths
    __shared__ uint32_t As[128 * 36];            // A tile [m][k]
    __shared__ uint32_t Bs[32 * 136];            // B tile [k][n]

    const int tid = threadIdx.x;
    const int wid = tid >> 5, lane = tid & 31;
    const int g = lane >> 2, tig = lane & 3;
    const int mW = (wid >> 2) * 64, nW = (wid & 3) * 32;
    const int bm = blockIdx.y * 128, bn = blockIdx.x * 128;

    float acc[4][4][4] = {};

    for (int k0 = 0; k0 < K; k0 += 32) {
        #pragma unroll
        for (int p = 0; p < 4; p++) {            // A: 128x32 = 1024 float4
            int v = tid + p * 256;
            int m = v >> 3, kc = (v & 7) * 4;
            float4 a = *(const float4*)&A[(size_t)(bm + m) * K + k0 + kc];
            uint32_t* d = &As[m * AP + kc];
            d[0] = f2t(a.x); d[1] = f2t(a.y); d[2] = f2t(a.z); d[3] = f2t(a.w);
        }
        #pragma unroll
        for (int p = 0; p < 4; p++) {            // B: 32x128 = 1024 float4
            int v = tid + p * 256;
            int kr = v >> 5, nc = (v & 31) * 4;
            float4 b = *(const float4*)&B[(size_t)(k0 + kr) * N + bn + nc];
            uint32_t* d = &Bs[kr * BP + nc];
            d[0] = f2t(b.x); d[1] = f2t(b.y); d[2] = f2t(b.z); d[3] = f2t(b.w);
        }
        __syncthreads();

        #pragma unroll
        for (int ks = 0; ks < 32; ks += 8) {
            uint32_t af[4][4], bf[4][2];
            #pragma unroll
            for (int mi = 0; mi < 4; mi++) {
                int r = mW + mi * 16 + g;
                af[mi][0] = As[r * AP + ks + tig];
                af[mi][1] = As[(r + 8) * AP + ks + tig];
                af[mi][2] = As[r * AP + ks + tig + 4];
                af[mi][3] = As[(r + 8) * AP + ks + tig + 4];
            }
            #pragma unroll
            for (int ni = 0; ni < 4; ni++) {
                int c = nW + ni * 8 + g;
                bf[ni][0] = Bs[(ks + tig) * BP + c];
                bf[ni][1] = Bs[(ks + tig + 4) * BP + c];
            }
            #pragma unroll
            for (int mi = 0; mi < 4; mi++)
                #pragma unroll
                for (int ni = 0; ni < 4; ni++)
                    mma8(acc[mi][ni], af[mi], bf[ni]);
        }
        __syncthreads();
    }

    #pragma unroll
    for (int mi = 0; mi < 4; mi++)
        #pragma unroll
        for (int ni = 0; ni < 4; ni++) {
            int r = bm + mW + mi * 16 + g;
            int c = bn + nW + ni * 8 + 2 * tig;
            *(float2*)&C[(size_t)r * N + c] =
                make_float2(acc[mi][ni][0], acc[mi][ni][1]);
            *(float2*)&C[(size_t)(r + 8) * N + c] =
                make_float2(acc[mi][ni][2], acc[mi][ni][3]);
        }
}

// ------- scores (NT, batched heads): S[h] = scale * Qh @ Kh^T -------------
// A = Qb + h*64 (M x 64, ld DM), B = Kb + h*64 (N x 64, ld DM)
__global__ void __launch_bounds__(256) gemm_nt_heads_tf32(
    const float* __restrict__ Qb, const float* __restrict__ Kb,
    float* __restrict__ Sb, int M, int N, float scale)
{
    const int P = 36;
    const int h = blockIdx.z;
    const float* A = Qb + h * DKH;
    const float* B = Kb + h * DKH;
    float* C = Sb + (size_t)h * M * N;

    __shared__ uint32_t As[128 * 36];            // Q tile [m][k]
    __shared__ uint32_t Bs[128 * 36];            // K tile [n][k]

    const int tid = threadIdx.x;
    const int wid = tid >> 5, lane = tid & 31;
    const int g = lane >> 2, tig = lane & 3;
    const int mW = (wid >> 2) * 64, nW = (wid & 3) * 32;
    const int bm = blockIdx.y * 128, bn = blockIdx.x * 128;

    float acc[4][4][4] = {};

    for (int k0 = 0; k0 < DKH; k0 += 32) {
        #pragma unroll
        for (int p = 0; p < 4; p++) {
            int v = tid + p * 256;
            int r = v >> 3, kc = (v & 7) * 4;
            float4 a = *(const float4*)&A[(size_t)(bm + r) * DM + k0 + kc];
            uint32_t* da = &As[r * P + kc];
            da[0] = f2t(a.x); da[1] = f2t(a.y); da[2] = f2t(a.z); da[3] = f2t(a.w);
            float4 b = *(const float4*)&B[(size_t)(bn + r) * DM + k0 + kc];
            uint32_t* db = &Bs[r * P + kc];
            db[0] = f2t(b.x); db[1] = f2t(b.y); db[2] = f2t(b.z); db[3] = f2t(b.w);
        }
        __syncthreads();

        #pragma unroll
        for (int ks = 0; ks < 32; ks += 8) {
            uint32_t af[4][4], bf[4][2];
            #pragma unroll
            for (int mi = 0; mi < 4; mi++) {
                int r = mW + mi * 16 + g;
                af[mi][0] = As[r * P + ks + tig];
                af[mi][1] = As[(r + 8) * P + ks + tig];
                af[mi][2] = As[r * P + ks + tig + 4];
                af[mi][3] = As[(r + 8) * P + ks + tig + 4];
            }
            #pragma unroll
            for (int ni = 0; ni < 4; ni++) {
                int c = nW + ni * 8 + g;
                bf[ni][0] = Bs[c * P + ks + tig];
                bf[ni][1] = Bs[c * P + ks + tig + 4];
            }
            #pragma unroll
            for (int mi = 0; mi < 4; mi++)
                #pragma unroll
                for (int ni = 0; ni < 4; ni++)
                    mma8(acc[mi][ni], af[mi], bf[ni]);
        }
        __syncthreads();
    }

    #pragma unroll
    for (int mi = 0; mi < 4; mi++)
        #pragma unroll
        for (int ni = 0; ni < 4; ni++) {
            int r = bm + mW + mi * 16 + g;
            int c = bn + nW + ni * 8 + 2 * tig;
            *(float2*)&C[(size_t)r * N + c] =
                make_float2(acc[mi][ni][0] * scale, acc[mi][ni][1] * scale);
            *(float2*)&C[(size_t)(r + 8) * N + c] =
                make_float2(acc[mi][ni][2] * scale, acc[mi][ni][3] * scale);
        }
}

// ------------- row softmax in place; L = NV*1024, one block/row ----------
template <int NV>
__global__ void __launch_bounds__(256) softmax_rows(float* __restrict__ S)
{
    const int L = NV * 1024;
    float* p = S + (size_t)blockIdx.x * L;
    const int tid = threadIdx.x;

    float4 v[NV];
    float mx = -1e30f;
    #pragma unroll
    for (int i = 0; i < NV; i++) {
        v[i] = *(const float4*)&p[(i * 256 + tid) * 4];
        mx = fmaxf(mx, fmaxf(fmaxf(v[i].x, v[i].y), fmaxf(v[i].z, v[i].w)));
    }

    __shared__ float redm[8], reds[8];
    #pragma unroll
    for (int o = 16; o > 0; o >>= 1) mx = fmaxf(mx, __shfl_xor_sync(0xffffffffu, mx, o));
    if ((tid & 31) == 0) redm[tid >> 5] = mx;
    __syncthreads();
    if (tid < 32) {
        float m = (tid < 8) ? redm[tid] : -1e30f;
        #pragma unroll
        for (int o = 4; o > 0; o >>= 1) m = fmaxf(m, __shfl_xor_sync(0xffffffffu, m, o));
        if (tid == 0) redm[0] = m;
    }
    __syncthreads();
    mx = redm[0];

    float sum = 0.f;
    #pragma unroll
    for (int i = 0; i < NV; i++) {
        v[i].x = __expf(v[i].x - mx);
        v[i].y = __expf(v[i].y - mx);
        v[i].z = __expf(v[i].z - mx);
        v[i].w = __expf(v[i].w - mx);
        sum += v[i].x + v[i].y + v[i].z + v[i].w;
    }
    #pragma unroll
    for (int o = 16; o > 0; o >>= 1) sum += __shfl_xor_sync(0xffffffffu, sum, o);
    if ((tid & 31) == 0) reds[tid >> 5] = sum;
    __syncthreads();
    if (tid < 32) {
        float s = (tid < 8) ? reds[tid] : 0.f;
        #pragma unroll
        for (int o = 4; o > 0; o >>= 1) s += __shfl_xor_sync(0xffffffffu, s, o);
        if (tid == 0) reds[0] = s;
    }
    __syncthreads();
    const float inv = 1.0f / reds[0];

    #pragma unroll
    for (int i = 0; i < NV; i++) {
        v[i].x *= inv; v[i].y *= inv; v[i].z *= inv; v[i].w *= inv;
        *(float4*)&p[(i * 256 + tid) * 4] = v[i];
    }
}

// ---- PV (batched heads), TRANSPOSED coalesced store: Ct[(h*64+d)*Nq+q] ---
// P = Pb + h*Nq*Nk (Nq x Nk), V = Vb + h*64 (Nk x 64, ld DM)
// Tile: 128(q) x 64(d), BK=32 keys, 8 warps (2m x 4n), warp tile 64x16.
__global__ void __launch_bounds__(256) pv_heads_tf32(
    const float* __restrict__ Pb, const float* __restrict__ Vb,
    float* __restrict__ Ct, int Nq, int Nk)
{
    const int AP = 36, BP = 72, CP = 132;
    __shared__ uint32_t sm[8448];                // max(As+Bs, Cs) in words
    uint32_t* As = sm;                           // P tile [q][k]  128x36
    uint32_t* Bs = sm + 128 * 36;                // V tile [k][d]  32x72
    float*    Cs = (float*)sm;                   // ctx transpose  64x132

    const int h = blockIdx.z;
    const float* P = Pb + (size_t)h * Nq * Nk;
    const float* V = Vb + h * DKH;
    const int bq = blockIdx.y * 128;

    const int tid = threadIdx.x;
    const int wid = tid >> 5, lane = tid & 31;
    const int g = lane >> 2, tig = lane & 3;
    const int mW = (wid >> 2) * 64, nW = (wid & 3) * 16;

    float acc[4][2][4] = {};

    for (int k0 = 0; k0 < Nk; k0 += 32) {
        #pragma unroll
        for (int p = 0; p < 4; p++) {            // P: 128x32 = 1024 float4
            int v = tid + p * 256;
            int q = v >> 3, kc = (v & 7) * 4;
            float4 a = *(const float4*)&P[(size_t)(bq + q) * Nk + k0 + kc];
            uint32_t* d = &As[q * AP + kc];
            d[0] = f2t(a.x); d[1] = f2t(a.y); d[2] = f2t(a.z); d[3] = f2t(a.w);
        }
        #pragma unroll
        for (int p = 0; p < 2; p++) {            // V: 32x64 = 512 float4
            int v = tid + p * 256;
            int kr = v >> 4, nc = (v & 15) * 4;
            float4 b = *(const float4*)&V[(size_t)(k0 + kr) * DM + nc];
            uint32_t* d = &Bs[kr * BP + nc];
            d[0] = f2t(b.x); d[1] = f2t(b.y); d[2] = f2t(b.z); d[3] = f2t(b.w);
        }
        __syncthreads();

        #pragma unroll
        for (int ks = 0; ks < 32; ks += 8) {
            uint32_t af[4][4], bf[2][2];
            #pragma unroll
            for (int mi = 0; mi < 4; mi++) {
                int r = mW + mi * 16 + g;
                af[mi][0] = As[r * AP + ks + tig];
                af[mi][1] = As[(r + 8) * AP + ks + tig];
                af[mi][2] = As[r * AP + ks + tig + 4];
                af[mi][3] = As[(r + 8) * AP + ks + tig + 4];
            }
            #pragma unroll
            for (int ni = 0; ni < 2; ni++) {
                int c = nW + ni * 8 + g;
                bf[ni][0] = Bs[(ks + tig) * BP + c];
                bf[ni][1] = Bs[(ks + tig + 4) * BP + c];
            }
            #pragma unroll
            for (int mi = 0; mi < 4; mi++)
                #pragma unroll
                for (int ni = 0; ni < 2; ni++)
                    mma8(acc[mi][ni], af[mi], bf[ni]);
        }
        __syncthreads();
    }

    // transpose through smem: Cs[d][q]
    #pragma unroll
    for (int mi = 0; mi < 4; mi++)
        #pragma unroll
        for (int ni = 0; ni < 2; ni++) {
            int q = mW + mi * 16 + g;
            int d = nW + ni * 8 + 2 * tig;
            Cs[d * CP + q]           = acc[mi][ni][0];
            Cs[(d + 1) * CP + q]     = acc[mi][ni][1];
            Cs[d * CP + q + 8]       = acc[mi][ni][2];
            Cs[(d + 1) * CP + q + 8] = acc[mi][ni][3];
        }
    __syncthreads();

    // coalesced store: 64 x 128 = 2048 float4
    const int hd = h * DKH;
    #pragma unroll
    for (int p = 0; p < 8; p++) {
        int v = tid + p * 256;
        int d = v >> 5, qv = (v & 31) * 4;
        *(float4*)&Ct[(size_t)(hd + d) * Nq + bq + qv] = *(float4*)&Cs[d * CP + qv];
    }
}

// --------------------------------- launch ---------------------------------
extern "C" void kernel_launch(void* const* d_in, const int* in_sizes, int n_in,
                              void* d_out, int out_size)
{
    const float* X    = (const float*)d_in[0];
    const float* X1   = (const float*)d_in[1];
    const float* WQ   = (const float*)d_in[2];
    const float* WK   = (const float*)d_in[3];
    const float* WV   = (const float*)d_in[4];
    const float* WQ1  = (const float*)d_in[5];
    const float* WK1  = (const float*)d_in[6];
    const float* WV1  = (const float*)d_in[7];
    const float* Wfc  = (const float*)d_in[8];
    const float* Wfc1 = (const float*)d_in[9];
    float* out = (float*)d_out;

    float *Q, *K, *V, *Q1, *K1, *V1, *S, *C, *C1;
    cudaGetSymbolAddress((void**)&Q,  g_Q);
    cudaGetSymbolAddress((void**)&K,  g_K);
    cudaGetSymbolAddress((void**)&V,  g_V);
    cudaGetSymbolAddress((void**)&Q1, g_Q1);
    cudaGetSymbolAddress((void**)&K1, g_K1);
    cudaGetSymbolAddress((void**)&V1, g_V1);
    cudaGetSymbolAddress((void**)&S,  g_S);
    cudaGetSymbolAddress((void**)&C,  g_C);
    cudaGetSymbolAddress((void**)&C1, g_C1);

    const dim3 blk(256);
    const float scale = 0.125f;   // 1/sqrt(64)

    // projections
    gemm_nn_tf32<<<dim3(DM / 128, N0 / 128),  blk>>>(X,  WQ,  Q,  N0,  DM, DM);
    gemm_nn_tf32<<<dim3(DM / 128, N0 / 128),  blk>>>(X,  WK,  K,  N0,  DM, DM);
    gemm_nn_tf32<<<dim3(DM / 128, N0 / 128),  blk>>>(X,  WV,  V,  N0,  DM, DM);
    gemm_nn_tf32<<<dim3(DM / 128, NN1 / 128), blk>>>(X1, WQ1, Q1, NN1, DM, DM);
    gemm_nn_tf32<<<dim3(DM / 128, NN1 / 128), blk>>>(X1, WK1, K1, NN1, DM, DM);
    gemm_nn_tf32<<<dim3(DM / 128, NN1 / 128), blk>>>(X1, WV1, V1, NN1, DM, DM);

    // direction 1: queries from X1 (N1 rows) attend over X (N0 keys)
    gemm_nt_heads_tf32<<<dim3(N0 / 128, NN1 / 128, NH), blk>>>(Q1, K, S, NN1, N0, scale);
    softmax_rows<2><<<NH * NN1, 256>>>(S);                        // L = 2048
    pv_heads_tf32<<<dim3(1, NN1 / 128, NH), blk>>>(S, V, C, NN1, N0);

    // direction 2: queries from X (N0 rows) attend over X1 (N1 keys)
    gemm_nt_heads_tf32<<<dim3(NN1 / 128, N0 / 128, NH), blk>>>(Q, K1, S, N0, NN1, scale);
    softmax_rows<3><<<NH * N0, 256>>>(S);                         // L = 3072
    pv_heads_tf32<<<dim3(1, N0 / 128, NH), blk>>>(S, V1, C1, N0, NN1);

    // final FCs (scrambled reshape == flat view of [H][DK][Nq] context)
    gemm_nn_tf32<<<dim3(DM / 128, NN1 / 128), blk>>>(C,  Wfc,  out,                    NN1, DM, DM);
    gemm_nn_tf32<<<dim3(DM / 128, N0 / 128),  blk>>>(C1, Wfc1, out + (size_t)NN1 * DM, N0,  DM, DM);
}

// round 3
// speedup vs baseline: 3.7479x; 1.6724x over previous
#include <cuda_runtime.h>
#include <cstdint>
#include <cstddef>

#define N0  2048
#define NN1 3072
#define DM  1024
#define NH  16
#define DKH 64

// ---------------- scratch (device globals; no allocation) ----------------
__device__ float g_Q [(size_t)N0 * DM];
__device__ float g_K [(size_t)N0 * DM];
__device__ float g_V [(size_t)N0 * DM];
__device__ float g_Q1[(size_t)NN1 * DM];
__device__ float g_K1[(size_t)NN1 * DM];
__device__ float g_V1[(size_t)NN1 * DM];
__device__ float g_C [(size_t)NN1 * DM];        // dir1 context, [H][DK][N1] flat
__device__ float g_C1[(size_t)N0 * DM];         // dir2 context, [H][DK][N0] flat

// --------------------------- tf32 helpers --------------------------------
__device__ __forceinline__ uint32_t f2t(float f) {
    uint32_t r;
    asm("cvt.rna.tf32.f32 %0, %1;" : "=r"(r) : "f"(f));
    return r;
}

__device__ __forceinline__ void mma8(float c[4], const uint32_t a[4], const uint32_t b[2]) {
    asm volatile(
        "mma.sync.aligned.m16n8k8.row.col.f32.tf32.tf32.f32 "
        "{%0,%1,%2,%3}, {%4,%5,%6,%7}, {%8,%9}, {%0,%1,%2,%3};"
        : "+f"(c[0]), "+f"(c[1]), "+f"(c[2]), "+f"(c[3])
        : "r"(a[0]), "r"(a[1]), "r"(a[2]), "r"(a[3]), "r"(b[0]), "r"(b[1]));
}

// ==================== batched NN GEMM (tf32, ping-pong) ===================
// Up to 3 independent GEMMs (same N=K=1024) selected by blockIdx.z.
// 128x128 tile, BK=32, 8 warps (2m x 4n), warp tile 64x32.
struct G3 {
    const float* A[3];
    const float* B[3];
    float*       C[3];
    int          M[3];
};

#define GEMM_BUF_WORDS (128 * 36 + 32 * 136)   // 8960 words per buffer
#define GEMM_SMEM_BYTES (2 * GEMM_BUF_WORDS * 4)

__global__ void __launch_bounds__(256) gemm3_tf32(G3 p, int N, int K)
{
    extern __shared__ uint32_t smU[];

    const int z = blockIdx.z;
    const float* __restrict__ A = p.A[z];
    const float* __restrict__ B = p.B[z];
    float* __restrict__ C = p.C[z];
    const int M = p.M[z];

    const int bm = blockIdx.y * 128;
    if (bm >= M) return;
    const int bn = blockIdx.x * 128;

    const int tid = threadIdx.x;
    const int wid = tid >> 5, lane = tid & 31;
    const int g = lane >> 2, t = lane & 3;
    const int mW = (wid >> 2) * 64, nW = (wid & 3) * 32;

    float acc[4][4][4] = {};
    float4 ra[4], rb[4];

    // prologue load tile 0
    #pragma unroll
    for (int pp = 0; pp < 4; pp++) {
        int v = tid + pp * 256;
        int m = v >> 3, kc = (v & 7) * 4;
        ra[pp] = *(const float4*)&A[(size_t)(bm + m) * K + kc];
        int kr = v >> 5, nc = (v & 31) * 4;
        rb[pp] = *(const float4*)&B[(size_t)kr * N + bn + nc];
    }
    {
        uint32_t* As = smU;
        uint32_t* Bs = smU + 128 * 36;
        #pragma unroll
        for (int pp = 0; pp < 4; pp++) {
            int v = tid + pp * 256;
            int m = v >> 3, kc = (v & 7) * 4;
            uint32_t* d = &As[m * 36 + kc];
            d[0] = f2t(ra[pp].x); d[1] = f2t(ra[pp].y);
            d[2] = f2t(ra[pp].z); d[3] = f2t(ra[pp].w);
            int kr = v >> 5, nc = (v & 31) * 4;
            uint32_t* e = &Bs[kr * 136 + nc];
            e[0] = f2t(rb[pp].x); e[1] = f2t(rb[pp].y);
            e[2] = f2t(rb[pp].z); e[3] = f2t(rb[pp].w);
        }
    }
    __syncthreads();

    int buf = 0;
    for (int k0 = 0; k0 < K; k0 += 32) {
        const bool more = (k0 + 32 < K);
        if (more) {
            #pragma unroll
            for (int pp = 0; pp < 4; pp++) {
                int v = tid + pp * 256;
                int m = v >> 3, kc = (v & 7) * 4;
                ra[pp] = *(const float4*)&A[(size_t)(bm + m) * K + k0 + 32 + kc];
                int kr = v >> 5, nc = (v & 31) * 4;
                rb[pp] = *(const float4*)&B[(size_t)(k0 + 32 + kr) * N + bn + nc];
            }
        }

        const uint32_t* As = smU + buf * GEMM_BUF_WORDS;
        const uint32_t* Bs = As + 128 * 36;

        #pragma unroll
        for (int ks = 0; ks < 32; ks += 8) {
            uint32_t af[4][4], bf[4][2];
            #pragma unroll
            for (int mi = 0; mi < 4; mi++) {
                int r = mW + mi * 16 + g;
                af[mi][0] = As[r * 36 + ks + t];
                af[mi][1] = As[(r + 8) * 36 + ks + t];
                af[mi][2] = As[r * 36 + ks + t + 4];
                af[mi][3] = As[(r + 8) * 36 + ks + t + 4];
            }
            #pragma unroll
            for (int ni = 0; ni < 4; ni++) {
                int c = nW + ni * 8 + g;
                bf[ni][0] = Bs[(ks + t) * 136 + c];
                bf[ni][1] = Bs[(ks + t + 4) * 136 + c];
            }
            #pragma unroll
            for (int mi = 0; mi < 4; mi++)
                #pragma unroll
                for (int ni = 0; ni < 4; ni++)
                    mma8(acc[mi][ni], af[mi], bf[ni]);
        }

        if (more) {
            uint32_t* Asn = smU + (buf ^ 1) * GEMM_BUF_WORDS;
            uint32_t* Bsn = Asn + 128 * 36;
            #pragma unroll
            for (int pp = 0; pp < 4; pp++) {
                int v = tid + pp * 256;
                int m = v >> 3, kc = (v & 7) * 4;
                uint32_t* d = &Asn[m * 36 + kc];
                d[0] = f2t(ra[pp].x); d[1] = f2t(ra[pp].y);
                d[2] = f2t(ra[pp].z); d[3] = f2t(ra[pp].w);
                int kr = v >> 5, nc = (v & 31) * 4;
                uint32_t* e = &Bsn[kr * 136 + nc];
                e[0] = f2t(rb[pp].x); e[1] = f2t(rb[pp].y);
                e[2] = f2t(rb[pp].z); e[3] = f2t(rb[pp].w);
            }
        }
        __syncthreads();
        buf ^= 1;
    }

    #pragma unroll
    for (int mi = 0; mi < 4; mi++)
        #pragma unroll
        for (int ni = 0; ni < 4; ni++) {
            int r = bm + mW + mi * 16 + g;
            int c = bn + nW + ni * 8 + 2 * t;
            *(float2*)&C[(size_t)r * N + c] =
                make_float2(acc[mi][ni][0], acc[mi][ni][1]);
            *(float2*)&C[(size_t)(r + 8) * N + c] =
                make_float2(acc[mi][ni][2], acc[mi][ni][3]);
        }
}

// ======================= fused flash cross-attention ======================
// grid (Nq/128, NH), block 256 (8 warps). Each warp owns 16 q-rows, Q held
// as register A-fragments (scale folded in). Streams 128-key K/V tiles,
// online softmax on mma accumulators, P->A-frag via intra-quad shuffles,
// context written TRANSPOSED (Ct[(h*64+d)*Nq + q]) via smem staging.
#define KP 68
#define VP 72
#define CP 132
#define FLASH_SMEM_BYTES ((128 * KP + 128 * VP) * 4)   // 71680

__global__ void __launch_bounds__(256) flash_attn_tf32(
    const float* __restrict__ Qg, const float* __restrict__ Kg,
    const float* __restrict__ Vg, float* __restrict__ Ct,
    int Nq, int Nk)
{
    extern __shared__ uint32_t smU[];
    uint32_t* Ks = smU;                 // 128 x KP (tf32 bits)
    uint32_t* Vs = smU + 128 * KP;      // 128 x VP

    const int h = blockIdx.y;
    const int bq = blockIdx.x * 128;
    const int tid = threadIdx.x;
    const int wid = tid >> 5, lane = tid & 31;
    const int g = lane >> 2, t = lane & 3;
    const int qw = wid * 16;

    // ---- stage Q (scaled by 1/8) into Ks, then pull A-fragments ----
    #pragma unroll
    for (int pp = 0; pp < 8; pp++) {
        int v = tid + pp * 256;
        int r = v >> 4, c4 = (v & 15) * 4;
        float4 q = *(const float4*)&Qg[(size_t)(bq + r) * DM + h * DKH + c4];
        uint32_t* d = &Ks[r * KP + c4];
        d[0] = f2t(q.x * 0.125f); d[1] = f2t(q.y * 0.125f);
        d[2] = f2t(q.z * 0.125f); d[3] = f2t(q.w * 0.125f);
    }
    __syncthreads();

    uint32_t aq[8][4];
    #pragma unroll
    for (int ks = 0; ks < 8; ks++) {
        aq[ks][0] = Ks[(qw + g) * KP + ks * 8 + t];
        aq[ks][1] = Ks[(qw + g + 8) * KP + ks * 8 + t];
        aq[ks][2] = Ks[(qw + g) * KP + ks * 8 + t + 4];
        aq[ks][3] = Ks[(qw + g + 8) * KP + ks * 8 + t + 4];
    }
    __syncthreads();

    float m0 = -1e30f, m1 = -1e30f, l0 = 0.f, l1 = 0.f;
    float o[8][4] = {};

    for (int kt = 0; kt < Nk; kt += 128) {
        // load K,V tiles (cvt at STS)
        #pragma unroll
        for (int pp = 0; pp < 8; pp++) {
            int v = tid + pp * 256;
            int r = v >> 4, c4 = (v & 15) * 4;
            float4 kk4 = *(const float4*)&Kg[(size_t)(kt + r) * DM + h * DKH + c4];
            uint32_t* d = &Ks[r * KP + c4];
            d[0] = f2t(kk4.x); d[1] = f2t(kk4.y); d[2] = f2t(kk4.z); d[3] = f2t(kk4.w);
            float4 vv4 = *(const float4*)&Vg[(size_t)(kt + r) * DM + h * DKH + c4];
            uint32_t* e = &Vs[r * VP + c4];
            e[0] = f2t(vv4.x); e[1] = f2t(vv4.y); e[2] = f2t(vv4.z); e[3] = f2t(vv4.w);
        }
        __syncthreads();

        // ---- S = (Q*scale) @ K^T : warp tile 16 x 128 ----
        float s[16][4] = {};
        #pragma unroll
        for (int ni = 0; ni < 16; ni++) {
            #pragma unroll
            for (int ks = 0; ks < 8; ks++) {
                uint32_t bf[2];
                bf[0] = Ks[(ni * 8 + g) * KP + ks * 8 + t];
                bf[1] = Ks[(ni * 8 + g) * KP + ks * 8 + t + 4];
                mma8(s[ni], aq[ks], bf);
            }
        }

        // ---- online softmax (rows g and g+8) ----
        float mx0 = -1e30f, mx1 = -1e30f;
        #pragma unroll
        for (int ni = 0; ni < 16; ni++) {
            mx0 = fmaxf(mx0, fmaxf(s[ni][0], s[ni][1]));
            mx1 = fmaxf(mx1, fmaxf(s[ni][2], s[ni][3]));
        }
        #pragma unroll
        for (int off = 1; off <= 2; off <<= 1) {
            mx0 = fmaxf(mx0, __shfl_xor_sync(0xffffffffu, mx0, off));
            mx1 = fmaxf(mx1, __shfl_xor_sync(0xffffffffu, mx1, off));
        }
        float mn0 = fmaxf(m0, mx0), mn1 = fmaxf(m1, mx1);
        float cr0 = __expf(m0 - mn0), cr1 = __expf(m1 - mn1);
        m0 = mn0; m1 = mn1;

        float rs0 = 0.f, rs1 = 0.f;
        #pragma unroll
        for (int ni = 0; ni < 16; ni++) {
            s[ni][0] = __expf(s[ni][0] - m0);
            s[ni][1] = __expf(s[ni][1] - m0);
            s[ni][2] = __expf(s[ni][2] - m1);
            s[ni][3] = __expf(s[ni][3] - m1);
            rs0 += s[ni][0] + s[ni][1];
            rs1 += s[ni][2] + s[ni][3];
        }
        #pragma unroll
        for (int off = 1; off <= 2; off <<= 1) {
            rs0 += __shfl_xor_sync(0xffffffffu, rs0, off);
            rs1 += __shfl_xor_sync(0xffffffffu, rs1, off);
        }
        l0 = l0 * cr0 + rs0;
        l1 = l1 * cr1 + rs1;

        #pragma unroll
        for (int dn = 0; dn < 8; dn++) {
            o[dn][0] *= cr0; o[dn][1] *= cr0;
            o[dn][2] *= cr1; o[dn][3] *= cr1;
        }

        // ---- O += P @ V ; P acc-layout -> A-frag via quad shuffles ----
        const int ln1 = (g << 2) | (t >> 1);
        const int ln2 = ln1 + 2;
        const bool odd = (t & 1);
        #pragma unroll
        for (int kk = 0; kk < 16; kk++) {
            float x0 = __shfl_sync(0xffffffffu, s[kk][0], ln1);
            float x1 = __shfl_sync(0xffffffffu, s[kk][1], ln1);
            float x2 = __shfl_sync(0xffffffffu, s[kk][2], ln1);
            float x3 = __shfl_sync(0xffffffffu, s[kk][3], ln1);
            float y0 = __shfl_sync(0xffffffffu, s[kk][0], ln2);
            float y1 = __shfl_sync(0xffffffffu, s[kk][1], ln2);
            float y2 = __shfl_sync(0xffffffffu, s[kk][2], ln2);
            float y3 = __shfl_sync(0xffffffffu, s[kk][3], ln2);
            uint32_t ap[4];
            ap[0] = f2t(odd ? x1 : x0);
            ap[1] = f2t(odd ? x3 : x2);
            ap[2] = f2t(odd ? y1 : y0);
            ap[3] = f2t(odd ? y3 : y2);
            #pragma unroll
            for (int dn = 0; dn < 8; dn++) {
                uint32_t bf[2];
                bf[0] = Vs[(kk * 8 + t) * VP + dn * 8 + g];
                bf[1] = Vs[(kk * 8 + t + 4) * VP + dn * 8 + g];
                mma8(o[dn], ap, bf);
            }
        }
        __syncthreads();
    }

    // ---- epilogue: normalize, transpose via smem, coalesced store ----
    const float i0 = 1.0f / l0, i1 = 1.0f / l1;
    float* Cs = (float*)smU;            // 64 x CP
    #pragma unroll
    for (int dn = 0; dn < 8; dn++) {
        int d = dn * 8 + 2 * t;
        Cs[d * CP + qw + g]           = o[dn][0] * i0;
        Cs[(d + 1) * CP + qw + g]     = o[dn][1] * i0;
        Cs[d * CP + qw + g + 8]       = o[dn][2] * i1;
        Cs[(d + 1) * CP + qw + g + 8] = o[dn][3] * i1;
    }
    __syncthreads();

    #pragma unroll
    for (int pp = 0; pp < 8; pp++) {
        int v = tid + pp * 256;
        int d = v >> 5, q4 = (v & 31) * 4;
        *(float4*)&Ct[(size_t)(h * DKH + d) * Nq + bq + q4] = *(float4*)&Cs[d * CP + q4];
    }
}

// --------------------------------- launch ---------------------------------
extern "C" void kernel_launch(void* const* d_in, const int* in_sizes, int n_in,
                              void* d_out, int out_size)
{
    const float* X    = (const float*)d_in[0];
    const float* X1   = (const float*)d_in[1];
    const float* WQ   = (const float*)d_in[2];
    const float* WK   = (const float*)d_in[3];
    const float* WV   = (const float*)d_in[4];
    const float* WQ1  = (const float*)d_in[5];
    const float* WK1  = (const float*)d_in[6];
    const float* WV1  = (const float*)d_in[7];
    const float* Wfc  = (const float*)d_in[8];
    const float* Wfc1 = (const float*)d_in[9];
    float* out = (float*)d_out;

    float *Q, *K, *V, *Q1, *K1, *V1, *C, *C1;
    cudaGetSymbolAddress((void**)&Q,  g_Q);
    cudaGetSymbolAddress((void**)&K,  g_K);
    cudaGetSymbolAddress((void**)&V,  g_V);
    cudaGetSymbolAddress((void**)&Q1, g_Q1);
    cudaGetSymbolAddress((void**)&K1, g_K1);
    cudaGetSymbolAddress((void**)&V1, g_V1);
    cudaGetSymbolAddress((void**)&C,  g_C);
    cudaGetSymbolAddress((void**)&C1, g_C1);

    static bool attr_done = false;
    if (!attr_done) {
        cudaFuncSetAttribute(gemm3_tf32,
            cudaFuncAttributeMaxDynamicSharedMemorySize, GEMM_SMEM_BYTES);
        cudaFuncSetAttribute(flash_attn_tf32,
            cudaFuncAttributeMaxDynamicSharedMemorySize, FLASH_SMEM_BYTES);
        attr_done = true;
    }

    const dim3 blk(256);

    // QKV projections: one launch per input, z selects W/out
    {
        G3 p;
        p.A[0] = X;  p.A[1] = X;  p.A[2] = X;
        p.B[0] = WQ; p.B[1] = WK; p.B[2] = WV;
        p.C[0] = Q;  p.C[1] = K;  p.C[2] = V;
        p.M[0] = N0; p.M[1] = N0; p.M[2] = N0;
        gemm3_tf32<<<dim3(DM / 128, N0 / 128, 3), blk, GEMM_SMEM_BYTES>>>(p, DM, DM);
    }
    {
        G3 p;
        p.A[0] = X1;  p.A[1] = X1;  p.A[2] = X1;
        p.B[0] = WQ1; p.B[1] = WK1; p.B[2] = WV1;
        p.C[0] = Q1;  p.C[1] = K1;  p.C[2] = V1;
        p.M[0] = NN1; p.M[1] = NN1; p.M[2] = NN1;
        gemm3_tf32<<<dim3(DM / 128, NN1 / 128, 3), blk, GEMM_SMEM_BYTES>>>(p, DM, DM);
    }

    // fused attention, both directions
    flash_attn_tf32<<<dim3(NN1 / 128, NH), blk, FLASH_SMEM_BYTES>>>(Q1, K, V, C, NN1, N0);
    flash_attn_tf32<<<dim3(N0 / 128, NH),  blk, FLASH_SMEM_BYTES>>>(Q, K1, V1, C1, N0, NN1);

    // final FCs in one launch (z=0: dir1, z=1: dir2; early-exit pads)
    {
        G3 p;
        p.A[0] = C;    p.A[1] = C1;   p.A[2] = C;
        p.B[0] = Wfc;  p.B[1] = Wfc1; p.B[2] = Wfc;
        p.C[0] = out;  p.C[1] = out + (size_t)NN1 * DM; p.C[2] = out;
        p.M[0] = NN1;  p.M[1] = N0;   p.M[2] = 0;
        gemm3_tf32<<<dim3(DM / 128, NN1 / 128, 2), blk, GEMM_SMEM_BYTES>>>(p, DM, DM);
    }
}

// round 4
// speedup vs baseline: 4.0170x; 1.0718x over previous
#include <cuda_runtime.h>
#include <cstdint>
#include <cstddef>

#define N0  2048
#define NN1 3072
#define DM  1024
#define NH  16
#define DKH 64

// ---------------- scratch (device globals; no allocation) ----------------
__device__ float g_Q [(size_t)N0 * DM];
__device__ float g_K [(size_t)N0 * DM];
__device__ float g_V [(size_t)N0 * DM];
__device__ float g_Q1[(size_t)NN1 * DM];
__device__ float g_K1[(size_t)NN1 * DM];
__device__ float g_V1[(size_t)NN1 * DM];
__device__ float g_C [(size_t)NN1 * DM];        // dir1 context, [H][DK][N1] flat
__device__ float g_C1[(size_t)N0 * DM];         // dir2 context, [H][DK][N0] flat

// --------------------------- tf32 helpers --------------------------------
__device__ __forceinline__ uint32_t f2t(float f) {
    uint32_t r;
    asm("cvt.rna.tf32.f32 %0, %1;" : "=r"(r) : "f"(f));
    return r;
}

__device__ __forceinline__ void mma8(float c[4], const uint32_t a[4], const uint32_t b[2]) {
    asm volatile(
        "mma.sync.aligned.m16n8k8.row.col.f32.tf32.tf32.f32 "
        "{%0,%1,%2,%3}, {%4,%5,%6,%7}, {%8,%9}, {%0,%1,%2,%3};"
        : "+f"(c[0]), "+f"(c[1]), "+f"(c[2]), "+f"(c[3])
        : "r"(a[0]), "r"(a[1]), "r"(a[2]), "r"(a[3]), "r"(b[0]), "r"(b[1]));
}

// ==================== batched NN GEMM (tf32, ping-pong) ===================
struct G3 {
    const float* A[3];
    const float* B[3];
    float*       C[3];
    int          M[3];
};

#define GEMM_BUF_WORDS (128 * 36 + 32 * 136)
#define GEMM_SMEM_BYTES (2 * GEMM_BUF_WORDS * 4)

__global__ void __launch_bounds__(256) gemm3_tf32(G3 p, int N, int K)
{
    extern __shared__ uint32_t smU[];

    const int z = blockIdx.z;
    const float* __restrict__ A = p.A[z];
    const float* __restrict__ B = p.B[z];
    float* __restrict__ C = p.C[z];
    const int M = p.M[z];

    const int bm = blockIdx.y * 128;
    if (bm >= M) return;
    const int bn = blockIdx.x * 128;

    const int tid = threadIdx.x;
    const int wid = tid >> 5, lane = tid & 31;
    const int g = lane >> 2, t = lane & 3;
    const int mW = (wid >> 2) * 64, nW = (wid & 3) * 32;

    float acc[4][4][4] = {};
    float4 ra[4], rb[4];

    #pragma unroll
    for (int pp = 0; pp < 4; pp++) {
        int v = tid + pp * 256;
        int m = v >> 3, kc = (v & 7) * 4;
        ra[pp] = *(const float4*)&A[(size_t)(bm + m) * K + kc];
        int kr = v >> 5, nc = (v & 31) * 4;
        rb[pp] = *(const float4*)&B[(size_t)kr * N + bn + nc];
    }
    {
        uint32_t* As = smU;
        uint32_t* Bs = smU + 128 * 36;
        #pragma unroll
        for (int pp = 0; pp < 4; pp++) {
            int v = tid + pp * 256;
            int m = v >> 3, kc = (v & 7) * 4;
            uint32_t* d = &As[m * 36 + kc];
            d[0] = f2t(ra[pp].x); d[1] = f2t(ra[pp].y);
            d[2] = f2t(ra[pp].z); d[3] = f2t(ra[pp].w);
            int kr = v >> 5, nc = (v & 31) * 4;
            uint32_t* e = &Bs[kr * 136 + nc];
            e[0] = f2t(rb[pp].x); e[1] = f2t(rb[pp].y);
            e[2] = f2t(rb[pp].z); e[3] = f2t(rb[pp].w);
        }
    }
    __syncthreads();

    int buf = 0;
    for (int k0 = 0; k0 < K; k0 += 32) {
        const bool more = (k0 + 32 < K);
        if (more) {
            #pragma unroll
            for (int pp = 0; pp < 4; pp++) {
                int v = tid + pp * 256;
                int m = v >> 3, kc = (v & 7) * 4;
                ra[pp] = *(const float4*)&A[(size_t)(bm + m) * K + k0 + 32 + kc];
                int kr = v >> 5, nc = (v & 31) * 4;
                rb[pp] = *(const float4*)&B[(size_t)(k0 + 32 + kr) * N + bn + nc];
            }
        }

        const uint32_t* As = smU + buf * GEMM_BUF_WORDS;
        const uint32_t* Bs = As + 128 * 36;

        #pragma unroll
        for (int ks = 0; ks < 32; ks += 8) {
            uint32_t af[4][4], bf[4][2];
            #pragma unroll
            for (int mi = 0; mi < 4; mi++) {
                int r = mW + mi * 16 + g;
                af[mi][0] = As[r * 36 + ks + t];
                af[mi][1] = As[(r + 8) * 36 + ks + t];
                af[mi][2] = As[r * 36 + ks + t + 4];
                af[mi][3] = As[(r + 8) * 36 + ks + t + 4];
            }
            #pragma unroll
            for (int ni = 0; ni < 4; ni++) {
                int c = nW + ni * 8 + g;
                bf[ni][0] = Bs[(ks + t) * 136 + c];
                bf[ni][1] = Bs[(ks + t + 4) * 136 + c];
            }
            #pragma unroll
            for (int mi = 0; mi < 4; mi++)
                #pragma unroll
                for (int ni = 0; ni < 4; ni++)
                    mma8(acc[mi][ni], af[mi], bf[ni]);
        }

        if (more) {
            uint32_t* Asn = smU + (buf ^ 1) * GEMM_BUF_WORDS;
            uint32_t* Bsn = Asn + 128 * 36;
            #pragma unroll
            for (int pp = 0; pp < 4; pp++) {
                int v = tid + pp * 256;
                int m = v >> 3, kc = (v & 7) * 4;
                uint32_t* d = &Asn[m * 36 + kc];
                d[0] = f2t(ra[pp].x); d[1] = f2t(ra[pp].y);
                d[2] = f2t(ra[pp].z); d[3] = f2t(ra[pp].w);
                int kr = v >> 5, nc = (v & 31) * 4;
                uint32_t* e = &Bsn[kr * 136 + nc];
                e[0] = f2t(rb[pp].x); e[1] = f2t(rb[pp].y);
                e[2] = f2t(rb[pp].z); e[3] = f2t(rb[pp].w);
            }
        }
        __syncthreads();
        buf ^= 1;
    }

    #pragma unroll
    for (int mi = 0; mi < 4; mi++)
        #pragma unroll
        for (int ni = 0; ni < 4; ni++) {
            int r = bm + mW + mi * 16 + g;
            int c = bn + nW + ni * 8 + 2 * t;
            *(float2*)&C[(size_t)r * N + c] =
                make_float2(acc[mi][ni][0], acc[mi][ni][1]);
            *(float2*)&C[(size_t)(r + 8) * N + c] =
                make_float2(acc[mi][ni][2], acc[mi][ni][3]);
        }
}

// ======================= fused flash cross-attention v2 ===================
// 128-thread CTA (4 warps), 2 CTAs/SM. Warp owns 32 q-rows (2 groups of 16).
// 64-key tiles. Q A-frags register-resident (scale*log2e folded). exp2-based
// online softmax. P reused as A-frag with ZERO shuffles via key permutation
// (V rows stored permuted). Context stored transposed via smem staging.
#define KP  68     // Ks/Qs row pad (words): bank = 4g+t  -> conflict-free
#define VP  72     // Vs row pad:            bank = 8t+g  -> conflict-free
#define CPW 132    // Cs row pad:            bank = 8t+g  -> conflict-free
#define FLASH_SMEM_WORDS (64 * KP + 64 * VP)   // 8960 words = 35840 B
#define QSC 0.18033688011112042f               // 0.125 * log2(e)

struct FA {
    const float* Q; const float* K; const float* V;
    float* Ct; int Nq; int Nk;
};

__global__ void __launch_bounds__(128, 2) flash2(FA a0, FA a1, int nbq0)
{
    __shared__ uint32_t sm[FLASH_SMEM_WORDS];
    uint32_t* Ks = sm;                  // 64 x KP
    uint32_t* Vs = sm + 64 * KP;        // 64 x VP

    const bool d1 = (blockIdx.x < nbq0);
    const FA a = d1 ? a0 : a1;
    const int bq = (d1 ? blockIdx.x : blockIdx.x - nbq0) * 128;
    const int h = blockIdx.y;
    const int Nq = a.Nq, Nk = a.Nk;
    const float* __restrict__ Qg = a.Q;
    const float* __restrict__ Kg = a.K;
    const float* __restrict__ Vg = a.V;

    const int tid = threadIdx.x;
    const int wid = tid >> 5, lane = tid & 31;
    const int g = lane >> 2, t = lane & 3;
    const int qw = wid * 32;

    // ---- stage Q (scaled) into sm[0..128*KP), pull A-frags ----
    #pragma unroll
    for (int pp = 0; pp < 16; pp++) {
        int idx = tid + pp * 128;
        int r = idx >> 4, c4 = (idx & 15) << 2;
        float4 q = *(const float4*)&Qg[(size_t)(bq + r) * DM + h * DKH + c4];
        uint4 u;
        u.x = f2t(q.x * QSC); u.y = f2t(q.y * QSC);
        u.z = f2t(q.z * QSC); u.w = f2t(q.w * QSC);
        *(uint4*)&sm[r * KP + c4] = u;
    }
    __syncthreads();

    uint32_t aq[2][8][4];
    #pragma unroll
    for (int grp = 0; grp < 2; grp++)
        #pragma unroll
        for (int ks = 0; ks < 8; ks++) {
            int r0 = qw + grp * 16 + g;
            aq[grp][ks][0] = sm[r0 * KP + ks * 8 + t];
            aq[grp][ks][1] = sm[(r0 + 8) * KP + ks * 8 + t];
            aq[grp][ks][2] = sm[r0 * KP + ks * 8 + t + 4];
            aq[grp][ks][3] = sm[(r0 + 8) * KP + ks * 8 + t + 4];
        }
    __syncthreads();

    float m[2][2], l[2][2];
    #pragma unroll
    for (int i = 0; i < 2; i++) { m[i][0] = m[i][1] = -1e30f; l[i][0] = l[i][1] = 0.f; }
    float o[2][8][4] = {};

    for (int kt = 0; kt < Nk; kt += 64) {
        // ---- load K (natural rows) and V (permuted rows) ----
        #pragma unroll
        for (int pp = 0; pp < 8; pp++) {
            int idx = tid + pp * 128;
            int r = idx >> 4, c4 = (idx & 15) << 2;
            float4 kv = *(const float4*)&Kg[(size_t)(kt + r) * DM + h * DKH + c4];
            uint4 uk;
            uk.x = f2t(kv.x); uk.y = f2t(kv.y); uk.z = f2t(kv.z); uk.w = f2t(kv.w);
            *(uint4*)&Ks[r * KP + c4] = uk;
            float4 vv = *(const float4*)&Vg[(size_t)(kt + r) * DM + h * DKH + c4];
            int pr = (r & 0x38) | ((r & 7) >> 1) | ((r & 1) << 2);
            uint4 uv;
            uv.x = f2t(vv.x); uv.y = f2t(vv.y); uv.z = f2t(vv.z); uv.w = f2t(vv.w);
            *(uint4*)&Vs[pr * VP + c4] = uv;
        }
        __syncthreads();

        // ---- S = Qs @ K^T (log2-domain scaled) ----
        float s[2][8][4] = {};
        #pragma unroll
        for (int ni = 0; ni < 8; ni++) {
            #pragma unroll
            for (int ks = 0; ks < 8; ks++) {
                uint32_t bf[2];
                bf[0] = Ks[(ni * 8 + g) * KP + ks * 8 + t];
                bf[1] = Ks[(ni * 8 + g) * KP + ks * 8 + t + 4];
                mma8(s[0][ni], aq[0][ks], bf);
                mma8(s[1][ni], aq[1][ks], bf);
            }
        }

        // ---- online softmax (base 2) ----
        #pragma unroll
        for (int grp = 0; grp < 2; grp++) {
            float mx0 = -1e30f, mx1 = -1e30f;
            #pragma unroll
            for (int ni = 0; ni < 8; ni++) {
                mx0 = fmaxf(mx0, fmaxf(s[grp][ni][0], s[grp][ni][1]));
                mx1 = fmaxf(mx1, fmaxf(s[grp][ni][2], s[grp][ni][3]));
            }
            #pragma unroll
            for (int off = 1; off <= 2; off <<= 1) {
                mx0 = fmaxf(mx0, __shfl_xor_sync(0xffffffffu, mx0, off));
                mx1 = fmaxf(mx1, __shfl_xor_sync(0xffffffffu, mx1, off));
            }
            float mn0 = fmaxf(m[grp][0], mx0), mn1 = fmaxf(m[grp][1], mx1);
            float cr0 = exp2f(m[grp][0] - mn0), cr1 = exp2f(m[grp][1] - mn1);
            m[grp][0] = mn0; m[grp][1] = mn1;

            float rs0 = 0.f, rs1 = 0.f;
            #pragma unroll
            for (int ni = 0; ni < 8; ni++) {
                s[grp][ni][0] = exp2f(s[grp][ni][0] - mn0);
                s[grp][ni][1] = exp2f(s[grp][ni][1] - mn0);
                s[grp][ni][2] = exp2f(s[grp][ni][2] - mn1);
                s[grp][ni][3] = exp2f(s[grp][ni][3] - mn1);
                rs0 += s[grp][ni][0] + s[grp][ni][1];
                rs1 += s[grp][ni][2] + s[grp][ni][3];
            }
            #pragma unroll
            for (int off = 1; off <= 2; off <<= 1) {
                rs0 += __shfl_xor_sync(0xffffffffu, rs0, off);
                rs1 += __shfl_xor_sync(0xffffffffu, rs1, off);
            }
            l[grp][0] = l[grp][0] * cr0 + rs0;
            l[grp][1] = l[grp][1] * cr1 + rs1;
            #pragma unroll
            for (int dn = 0; dn < 8; dn++) {
                o[grp][dn][0] *= cr0; o[grp][dn][1] *= cr0;
                o[grp][dn][2] *= cr1; o[grp][dn][3] *= cr1;
            }
        }

        // ---- O += P @ V (P acc-layout == A-frag under key permutation) ----
        #pragma unroll
        for (int kk = 0; kk < 8; kk++) {
            uint32_t ap0[4], ap1[4];
            ap0[0] = f2t(s[0][kk][0]); ap0[1] = f2t(s[0][kk][2]);
            ap0[2] = f2t(s[0][kk][1]); ap0[3] = f2t(s[0][kk][3]);
            ap1[0] = f2t(s[1][kk][0]); ap1[1] = f2t(s[1][kk][2]);
            ap1[2] = f2t(s[1][kk][1]); ap1[3] = f2t(s[1][kk][3]);
            #pragma unroll
            for (int dn = 0; dn < 8; dn++) {
                uint32_t bf[2];
                bf[0] = Vs[(kk * 8 + t) * VP + dn * 8 + g];
                bf[1] = Vs[(kk * 8 + t + 4) * VP + dn * 8 + g];
                mma8(o[0][dn], ap0, bf);
                mma8(o[1][dn], ap1, bf);
            }
        }
        __syncthreads();
    }

    // ---- epilogue: normalize, transpose via smem, coalesced store ----
    float* Cs = (float*)sm;             // 64 x CPW
    #pragma unroll
    for (int grp = 0; grp < 2; grp++) {
        float i0 = 1.0f / l[grp][0], i1 = 1.0f / l[grp][1];
        int q = qw + grp * 16 + g;
        #pragma unroll
        for (int dn = 0; dn < 8; dn++) {
            int d = dn * 8 + 2 * t;
            Cs[d * CPW + q]           = o[grp][dn][0] * i0;
            Cs[(d + 1) * CPW + q]     = o[grp][dn][1] * i0;
            Cs[d * CPW + q + 8]       = o[grp][dn][2] * i1;
            Cs[(d + 1) * CPW + q + 8] = o[grp][dn][3] * i1;
        }
    }
    __syncthreads();

    float* Ct = a.Ct;
    #pragma unroll
    for (int pp = 0; pp < 16; pp++) {
        int idx = tid + pp * 128;
        int d = idx >> 5, q4 = (idx & 31) * 4;
        *(float4*)&Ct[(size_t)(h * DKH + d) * Nq + bq + q4] = *(float4*)&Cs[d * CPW + q4];
    }
}

// --------------------------------- launch ---------------------------------
extern "C" void kernel_launch(void* const* d_in, const int* in_sizes, int n_in,
                              void* d_out, int out_size)
{
    const float* X    = (const float*)d_in[0];
    const float* X1   = (const float*)d_in[1];
    const float* WQ   = (const float*)d_in[2];
    const float* WK   = (const float*)d_in[3];
    const float* WV   = (const float*)d_in[4];
    const float* WQ1  = (const float*)d_in[5];
    const float* WK1  = (const float*)d_in[6];
    const float* WV1  = (const float*)d_in[7];
    const float* Wfc  = (const float*)d_in[8];
    const float* Wfc1 = (const float*)d_in[9];
    float* out = (float*)d_out;

    float *Q, *K, *V, *Q1, *K1, *V1, *C, *C1;
    cudaGetSymbolAddress((void**)&Q,  g_Q);
    cudaGetSymbolAddress((void**)&K,  g_K);
    cudaGetSymbolAddress((void**)&V,  g_V);
    cudaGetSymbolAddress((void**)&Q1, g_Q1);
    cudaGetSymbolAddress((void**)&K1, g_K1);
    cudaGetSymbolAddress((void**)&V1, g_V1);
    cudaGetSymbolAddress((void**)&C,  g_C);
    cudaGetSymbolAddress((void**)&C1, g_C1);

    static bool attr_done = false;
    if (!attr_done) {
        cudaFuncSetAttribute(gemm3_tf32,
            cudaFuncAttributeMaxDynamicSharedMemorySize, GEMM_SMEM_BYTES);
        attr_done = true;
    }

    const dim3 blk(256);

    // QKV projections
    {
        G3 p;
        p.A[0] = X;  p.A[1] = X;  p.A[2] = X;
        p.B[0] = WQ; p.B[1] = WK; p.B[2] = WV;
        p.C[0] = Q;  p.C[1] = K;  p.C[2] = V;
        p.M[0] = N0; p.M[1] = N0; p.M[2] = N0;
        gemm3_tf32<<<dim3(DM / 128, N0 / 128, 3), blk, GEMM_SMEM_BYTES>>>(p, DM, DM);
    }
    {
        G3 p;
        p.A[0] = X1;  p.A[1] = X1;  p.A[2] = X1;
        p.B[0] = WQ1; p.B[1] = WK1; p.B[2] = WV1;
        p.C[0] = Q1;  p.C[1] = K1;  p.C[2] = V1;
        p.M[0] = NN1; p.M[1] = NN1; p.M[2] = NN1;
        gemm3_tf32<<<dim3(DM / 128, NN1 / 128, 3), blk, GEMM_SMEM_BYTES>>>(p, DM, DM);
    }

    // fused attention: both directions in ONE launch (wave balance)
    {
        FA a0, a1;
        a0.Q = Q1; a0.K = K;  a0.V = V;  a0.Ct = C;  a0.Nq = NN1; a0.Nk = N0;
        a1.Q = Q;  a1.K = K1; a1.V = V1; a1.Ct = C1; a1.Nq = N0;  a1.Nk = NN1;
        const int nbq0 = NN1 / 128;                  // 24
        const int nbq1 = N0 / 128;                   // 16
        flash2<<<dim3(nbq0 + nbq1, NH), dim3(128)>>>(a0, a1, nbq0);
    }

    // final FCs in one launch
    {
        G3 p;
        p.A[0] = C;    p.A[1] = C1;   p.A[2] = C;
        p.B[0] = Wfc;  p.B[1] = Wfc1; p.B[2] = Wfc;
        p.C[0] = out;  p.C[1] = out + (size_t)NN1 * DM; p.C[2] = out;
        p.M[0] = NN1;  p.M[1] = N0;   p.M[2] = 0;
        gemm3_tf32<<<dim3(DM / 128, NN1 / 128, 2), blk, GEMM_SMEM_BYTES>>>(p, DM, DM);
    }
}